// round 4
// baseline (speedup 1.0000x reference)
#include <cuda_runtime.h>
#include <cuda_fp16.h>
#include <cstdint>

// ============================================================================
// Gating_37598143709808 v4: compute_100-safe (no tcgen05 — harness emits
// family-agnostic PTX). Ampere-style mma.sync fp16 GEMM, split-fp16 3-pass
// for fp32-grade accuracy, persistent CTAs, W1hi resident in SMEM, W1lo
// streamed via cp.async, fully fused epilogue (relu + second GEMM + top-2 +
// softmax + scatter).
//   h = relu(x@W1+b1); logits = h@W2+b2; top2 -> softmax -> scatter.
// B=262144, D=H=256, E=5, K=2.
// ============================================================================

#define LO_SCALE 2048.0f          // 2^11: keep lo parts in fp16 normal range
#define LO_INV   (1.0f / 2048.0f)

static __device__ __forceinline__ uint32_t smem_u32(const void* p) {
    uint32_t a;
    asm("{ .reg .u64 t; cvta.to.shared.u64 t, %1; cvt.u32.u64 %0, t; }"
        : "=r"(a) : "l"(p));
    return a;
}

// ldmatrix x4 (A fragments, m-major smem) and x4.trans (B fragments, k-major smem)
#define LDSM_X4(r, addr) \
    asm volatile("ldmatrix.sync.aligned.m8n8.x4.shared.b16 {%0,%1,%2,%3}, [%4];" \
        : "=r"((r)[0]), "=r"((r)[1]), "=r"((r)[2]), "=r"((r)[3]) : "r"(addr))
#define LDSM_X4T(r, addr) \
    asm volatile("ldmatrix.sync.aligned.m8n8.x4.trans.shared.b16 {%0,%1,%2,%3}, [%4];" \
        : "=r"((r)[0]), "=r"((r)[1]), "=r"((r)[2]), "=r"((r)[3]) : "r"(addr))

// mma.sync m16n8k16 fp16 x fp16 -> fp32, accumulate in place
#define MMA(acc, a, b0_, b1_) \
    asm volatile("mma.sync.aligned.m16n8k16.row.col.f32.f16.f16.f32 " \
        "{%0,%1,%2,%3},{%4,%5,%6,%7},{%8,%9},{%0,%1,%2,%3};" \
        : "+f"((acc)[0]), "+f"((acc)[1]), "+f"((acc)[2]), "+f"((acc)[3]) \
        : "r"((a)[0]), "r"((a)[1]), "r"((a)[2]), "r"((a)[3]), "r"(b0_), "r"(b1_))

// cp.async (sm_80+, compute_100-safe)
#define CP_ASYNC16(dst, src) \
    asm volatile("cp.async.cg.shared.global [%0], [%1], 16;" \
                 :: "r"(dst), "l"(src) : "memory")
#define CP_COMMIT() asm volatile("cp.async.commit_group;" ::: "memory")
#define CP_WAIT0()  asm volatile("cp.async.wait_group 0;"  ::: "memory")

// ---------------------------------------------------------------------------
// Prepped W1 splits in device globals, ORIGINAL [K=256][N=256] layout
// (k-major is exactly what the B-operand smem wants — no transpose).
// lo part pre-scaled by 2^11.
// ---------------------------------------------------------------------------
__device__ __align__(16) __half g_W1hi[256 * 256];
__device__ __align__(16) __half g_W1lo[256 * 256];

__global__ void prep_w1_kernel(const float* __restrict__ W1) {
    int idx = blockIdx.x * 256 + threadIdx.x;   // 0..65535
    float v  = W1[idx];
    __half hi = __float2half_rn(v);
    float  r  = (v - __half2float(hi)) * LO_SCALE;
    g_W1hi[idx] = hi;
    g_W1lo[idx] = __float2half_rn(r);
}

// ---------------------------------------------------------------------------
// SMEM layout (dynamic, 192 KB)
// ---------------------------------------------------------------------------
#define OFF_B1P   0          // 128 float2 (b1 col-pairs)            1 KB
#define OFF_W2P   1024       // 128*5 float2 (W2 col-pairs x expert) 5 KB
#define OFF_B2    6144       // 5 floats
#define OFF_PART  6272       // [4 warpN][64 rows][5] floats         5 KB
#define OFF_AHI   11520      // 2 buf x [64 m][80B] (32 k fp16)     10 KB
#define OFF_ALO   21760      //                                     10 KB
#define OFF_BLO   32768      // 2 buf x [32 k][512B] (256 n fp16)   32 KB
#define OFF_W1HI  65536      // [256 k][512B] XOR-swizzled         128 KB
#define SMEM_BYTES 196608

__global__ __launch_bounds__(256, 1)
void gating_main(const float* __restrict__ x,
                 const float* __restrict__ b1,
                 const float* __restrict__ W2,
                 const float* __restrict__ b2,
                 float* __restrict__ gates_out,
                 float* __restrict__ idx_out,
                 int ntiles)
{
    extern __shared__ __align__(1024) char smem[];
    const uint32_t sb = smem_u32(smem);
    const int tid   = threadIdx.x;
    const int lane  = tid & 31;
    const int wid   = tid >> 5;
    const int warpM = wid >> 2;      // 0..1  (32 rows each)
    const int warpN = wid & 3;       // 0..3  (64 cols each)

    // ---- Stage small tensors ----
    if (tid < 128) {
        ((float2*)(smem + OFF_B1P))[tid] = make_float2(b1[2 * tid], b1[2 * tid + 1]);
    }
    for (int u = tid; u < 640; u += 256) {       // w2pair[p*5+e] = {W2[2p][e], W2[2p+1][e]}
        int p = u / 5, e = u - p * 5;
        ((float2*)(smem + OFF_W2P))[u] =
            make_float2(W2[2 * p * 5 + e], W2[(2 * p + 1) * 5 + e]);
    }
    if (tid < 5) ((float*)(smem + OFF_B2))[tid] = b2[tid];

    // ---- Stage resident W1hi: [k][n] fp16, 512B rows, 16B-chunk XOR swizzle ----
    #pragma unroll 4
    for (int i = 0; i < 32; i++) {
        int u = tid + 256 * i;                   // 8192 x 16B
        int k = u >> 5;
        int j = u & 31;                          // n-chunk (8 fp16)
        uint4 v = *((const uint4*)(g_W1hi) + (k * 32 + j));
        *(uint4*)(smem + OFF_W1HI + k * 512 + ((j ^ (k & 7)) << 4)) = v;
    }
    __syncthreads();

    // ---- Per-lane ldmatrix address components ----
    const int a_row  = lane & 15;                // row within m16
    const int a_col8 = (lane >> 4) << 4;         // 8-elem k group -> bytes
    const int b_krow = lane & 15;                // k row within k16
    const int b_n    = warpN * 64 + ((lane >> 4) << 3);  // +p*16 later

    // x load coords: thread -> (row 0..63, 8-float group 0..3)
    const int xrow = tid >> 2;
    const int xg   = tid & 3;

    // ------------------------------------------------------------------
    // Persistent tile loop: tiles of 64 rows.
    // ------------------------------------------------------------------
    for (int g = blockIdx.x; g < ntiles; g += gridDim.x) {
        const int m0 = g * 64;

        float acc_h[2][8][4];   // hi*hi
        float acc_x[2][8][4];   // hi*lo + lo*hi (scaled by 2^11)
        #pragma unroll
        for (int mi = 0; mi < 2; mi++)
            #pragma unroll
            for (int nf = 0; nf < 8; nf++)
                #pragma unroll
                for (int c = 0; c < 4; c++) { acc_h[mi][nf][c] = 0.f; acc_x[mi][nf][c] = 0.f; }

        float4 xr0, xr1;        // 8 floats of x (prefetch regs)

        auto load_x = [&](int kc) {
            const float* src = x + (size_t)(m0 + xrow) * 256 + kc * 32 + xg * 8;
            xr0 = *(const float4*)(src);
            xr1 = *(const float4*)(src + 4);
        };
        auto store_x = [&](int buf) {
            float vv[8] = {xr0.x, xr0.y, xr0.z, xr0.w, xr1.x, xr1.y, xr1.z, xr1.w};
            ushort hh[8], ll[8];
            #pragma unroll
            for (int p = 0; p < 8; p++) {
                __half h = __float2half_rn(vv[p]);
                __half l = __float2half_rn((vv[p] - __half2float(h)) * LO_SCALE);
                hh[p] = __half_as_ushort(h);
                ll[p] = __half_as_ushort(l);
            }
            uint4 hv = make_uint4((uint32_t)hh[0] | ((uint32_t)hh[1] << 16),
                                  (uint32_t)hh[2] | ((uint32_t)hh[3] << 16),
                                  (uint32_t)hh[4] | ((uint32_t)hh[5] << 16),
                                  (uint32_t)hh[6] | ((uint32_t)hh[7] << 16));
            uint4 lv = make_uint4((uint32_t)ll[0] | ((uint32_t)ll[1] << 16),
                                  (uint32_t)ll[2] | ((uint32_t)ll[3] << 16),
                                  (uint32_t)ll[4] | ((uint32_t)ll[5] << 16),
                                  (uint32_t)ll[6] | ((uint32_t)ll[7] << 16));
            *(uint4*)(smem + OFF_AHI + buf * 5120 + xrow * 80 + xg * 16) = hv;
            *(uint4*)(smem + OFF_ALO + buf * 5120 + xrow * 80 + xg * 16) = lv;
        };
        // W1lo chunk: 32k x 256n fp16 = 1024 x 16B, cp.async straight to SMEM.
        auto cp_blo = [&](int kc, int buf) {
            #pragma unroll
            for (int i = 0; i < 4; i++) {
                int u  = tid + 256 * i;
                int kl = u >> 5;
                int j  = u & 31;
                uint32_t dst = sb + OFF_BLO + buf * 16384 + kl * 512 +
                               (uint32_t)((j ^ (kl & 7)) << 4);
                const uint4* src = (const uint4*)(g_W1lo) + ((kc * 32 + kl) * 32 + j);
                CP_ASYNC16(dst, src);
            }
            CP_COMMIT();
        };

        // Prologue: chunk 0 into buffer 0.
        load_x(0);
        cp_blo(0, 0);
        store_x(0);

        #pragma unroll 1
        for (int kc = 0; kc < 8; kc++) {
            const int buf = kc & 1;
            CP_WAIT0();                          // my cp.async group for buf done
            __syncthreads();                     // cta-wide: STS + cp.async visible
            if (kc < 7) {
                cp_blo(kc + 1, buf ^ 1);         // overlap with MMA block below
                load_x(kc + 1);                  // LDG latency hidden by MMAs
            }

            #pragma unroll
            for (int k16 = 0; k16 < 2; k16++) {
                uint32_t ah[2][4], al[2][4], bh[4][4], blr[4][4];
                #pragma unroll
                for (int mi = 0; mi < 2; mi++) {
                    uint32_t aoff = (uint32_t)((warpM * 32 + mi * 16 + a_row) * 80 +
                                               k16 * 32 + a_col8);
                    LDSM_X4(ah[mi], sb + OFF_AHI + buf * 5120 + aoff);
                    LDSM_X4(al[mi], sb + OFF_ALO + buf * 5120 + aoff);
                }
                #pragma unroll
                for (int p = 0; p < 4; p++) {
                    int n_col = b_n + p * 16;
                    int k_abs = kc * 32 + k16 * 16 + b_krow;
                    int k_loc = k16 * 16 + b_krow;
                    uint32_t hoff = (uint32_t)(k_abs * 512 +
                                               (((n_col >> 3) ^ (k_abs & 7)) << 4));
                    uint32_t loff = (uint32_t)(k_loc * 512 +
                                               (((n_col >> 3) ^ (k_loc & 7)) << 4));
                    LDSM_X4T(bh[p],  sb + OFF_W1HI + hoff);
                    LDSM_X4T(blr[p], sb + OFF_BLO + buf * 16384 + loff);
                }
                #pragma unroll
                for (int mi = 0; mi < 2; mi++) {
                    #pragma unroll
                    for (int p = 0; p < 4; p++) {
                        MMA(acc_h[mi][2 * p],     ah[mi], bh[p][0],  bh[p][1]);
                        MMA(acc_h[mi][2 * p + 1], ah[mi], bh[p][2],  bh[p][3]);
                        MMA(acc_x[mi][2 * p],     ah[mi], blr[p][0], blr[p][1]);
                        MMA(acc_x[mi][2 * p + 1], ah[mi], blr[p][2], blr[p][3]);
                        MMA(acc_x[mi][2 * p],     al[mi], bh[p][0],  bh[p][1]);
                        MMA(acc_x[mi][2 * p + 1], al[mi], bh[p][2],  bh[p][3]);
                    }
                }
            }
            if (kc < 7) store_x(buf ^ 1);        // other buffer; safe w/o extra sync
        }

        // -------------------- Epilogue --------------------
        const float2* b1pr = (const float2*)(smem + OFF_B1P);
        const float2* w2pr = (const float2*)(smem + OFF_W2P);

        float lg[4][5];
        #pragma unroll
        for (int r = 0; r < 4; r++)
            #pragma unroll
            for (int e = 0; e < 5; e++) lg[r][e] = 0.f;

        #pragma unroll
        for (int nf = 0; nf < 8; nf++) {
            const int pidx = warpN * 32 + nf * 4 + (lane & 3);
            const float2 b1p = b1pr[pidx];
            float2 w2v[5];
            #pragma unroll
            for (int e = 0; e < 5; e++) w2v[e] = w2pr[pidx * 5 + e];
            #pragma unroll
            for (int mi = 0; mi < 2; mi++) {
                #pragma unroll
                for (int ch = 0; ch < 2; ch++) {
                    float h0 = fmaxf(fmaf(acc_x[mi][nf][ch * 2 + 0], LO_INV,
                                          acc_h[mi][nf][ch * 2 + 0]) + b1p.x, 0.f);
                    float h1 = fmaxf(fmaf(acc_x[mi][nf][ch * 2 + 1], LO_INV,
                                          acc_h[mi][nf][ch * 2 + 1]) + b1p.y, 0.f);
                    const int r = mi * 2 + ch;
                    #pragma unroll
                    for (int e = 0; e < 5; e++)
                        lg[r][e] = fmaf(h1, w2v[e].y, fmaf(h0, w2v[e].x, lg[r][e]));
                }
            }
        }
        // quad reduce (4 col-pairs within warp share a row)
        #pragma unroll
        for (int r = 0; r < 4; r++)
            #pragma unroll
            for (int e = 0; e < 5; e++) {
                lg[r][e] += __shfl_xor_sync(0xFFFFFFFFu, lg[r][e], 1);
                lg[r][e] += __shfl_xor_sync(0xFFFFFFFFu, lg[r][e], 2);
            }
        float* part = (float*)(smem + OFF_PART);
        if ((lane & 3) == 0) {
            #pragma unroll
            for (int mi = 0; mi < 2; mi++)
                #pragma unroll
                for (int ch = 0; ch < 2; ch++) {
                    int row = warpM * 32 + mi * 16 + ch * 8 + (lane >> 2);
                    int r = mi * 2 + ch;
                    #pragma unroll
                    for (int e = 0; e < 5; e++)
                        part[(warpN * 64 + row) * 5 + e] = lg[r][e];
                }
        }
        __syncthreads();

        if (tid < 64) {
            const float* b2s = (const float*)(smem + OFF_B2);
            float l[5];
            #pragma unroll
            for (int e = 0; e < 5; e++)
                l[e] = part[(0 * 64 + tid) * 5 + e] + part[(1 * 64 + tid) * 5 + e] +
                       part[(2 * 64 + tid) * 5 + e] + part[(3 * 64 + tid) * 5 + e] +
                       b2s[e];

            // top-2, jax tie semantics (strict >, lowest index wins)
            float v1 = -3.4e38f, v2 = -3.4e38f;
            int i1 = -1, i2 = -1;
            #pragma unroll
            for (int e = 0; e < 5; e++) {
                if (l[e] > v1)      { v2 = v1; i2 = i1; v1 = l[e]; i1 = e; }
                else if (l[e] > v2) { v2 = l[e]; i2 = e; }
            }
            float e2v = expf(v2 - v1);
            float s   = 1.0f + e2v;
            float g1  = 1.0f / s;
            float g2  = e2v / s;

            size_t rg = (size_t)m0 + tid;
            if (gates_out) {
                #pragma unroll
                for (int e = 0; e < 5; e++) {
                    float gv = (e == i1) ? g1 : ((e == i2) ? g2 : 0.0f);
                    gates_out[rg * 5 + e] = gv;
                }
            }
            if (idx_out) {
                idx_out[rg * 2 + 0] = (float)i1;
                idx_out[rg * 2 + 1] = (float)i2;
            }
        }
        __syncthreads();   // protect 'part' and smem bufs before next tile
    }
}

// ---------------------------------------------------------------------------
// Launch. Inputs (metadata order): x, W1, b1, W2, b2.
// Output assumed: gates [B*5] floats, then top_idx [B*2] as floats.
// ---------------------------------------------------------------------------
extern "C" void kernel_launch(void* const* d_in, const int* in_sizes, int n_in,
                              void* d_out, int out_size)
{
    const float* x  = (const float*)d_in[0];
    const float* W1 = (const float*)d_in[1];
    const float* b1 = (const float*)d_in[2];
    const float* W2 = (const float*)d_in[3];
    const float* b2 = (const float*)d_in[4];

    const int B = in_sizes[0] / 256;
    const int ntiles = B / 64;

    float* out       = (float*)d_out;
    float* gates_out = out;
    float* idx_out   = nullptr;
    if (out_size >= B * 7) {
        idx_out = out + (size_t)B * 5;          // gates then idx (concatenated)
    } else if (out_size == B * 2) {
        gates_out = nullptr;                    // idx only
        idx_out   = out;
    }                                           // else: gates only

    cudaFuncSetAttribute(gating_main,
                         cudaFuncAttributeMaxDynamicSharedMemorySize, SMEM_BYTES);

    prep_w1_kernel<<<256, 256>>>(W1);

    int grid = 148;
    if (grid > ntiles) grid = ntiles;
    gating_main<<<grid, 256, SMEM_BYTES>>>(x, b1, W2, b2, gates_out, idx_out, ntiles);
}

// round 6
// speedup vs baseline: 1.0333x; 1.0333x over previous
#include <cuda_runtime.h>
#include <cuda_fp16.h>
#include <cstdint>

// ============================================================================
// Gating_37598143709808 v5b: 512-thread CTAs (16 warps, 4/SMSP) for tensor-
// pipe latency hiding. Ampere-style mma.sync fp16 GEMM (compute_100-safe),
// split-fp16 3-pass for fp32-grade accuracy, persistent CTAs, W1hi resident
// in SMEM, W1lo streamed via cp.async, fully fused epilogue.
//   h = relu(x@W1+b1); logits = h@W2+b2; top2 -> softmax -> scatter.
// B=262144, D=H=256, E=5, K=2.
// v4 (256 thr): 353.7us, tensor=52.4%, occ=12.5%. v5b targets ~85% tensor.
// ============================================================================

#define LO_SCALE 2048.0f          // 2^11: keep lo parts in fp16 normal range
#define LO_INV   (1.0f / 2048.0f)

static __device__ __forceinline__ uint32_t smem_u32(const void* p) {
    uint32_t a;
    asm("{ .reg .u64 t; cvta.to.shared.u64 t, %1; cvt.u32.u64 %0, t; }"
        : "=r"(a) : "l"(p));
    return a;
}

// ldmatrix x4 (A fragments, m-major smem) and x4.trans (B fragments, k-major smem)
#define LDSM_X4(r, addr) \
    asm volatile("ldmatrix.sync.aligned.m8n8.x4.shared.b16 {%0,%1,%2,%3}, [%4];" \
        : "=r"((r)[0]), "=r"((r)[1]), "=r"((r)[2]), "=r"((r)[3]) : "r"(addr))
#define LDSM_X4T(r, addr) \
    asm volatile("ldmatrix.sync.aligned.m8n8.x4.trans.shared.b16 {%0,%1,%2,%3}, [%4];" \
        : "=r"((r)[0]), "=r"((r)[1]), "=r"((r)[2]), "=r"((r)[3]) : "r"(addr))

// mma.sync m16n8k16 fp16 x fp16 -> fp32, accumulate in place
#define MMA(acc, a, b0_, b1_) \
    asm volatile("mma.sync.aligned.m16n8k16.row.col.f32.f16.f16.f32 " \
        "{%0,%1,%2,%3},{%4,%5,%6,%7},{%8,%9},{%0,%1,%2,%3};" \
        : "+f"((acc)[0]), "+f"((acc)[1]), "+f"((acc)[2]), "+f"((acc)[3]) \
        : "r"((a)[0]), "r"((a)[1]), "r"((a)[2]), "r"((a)[3]), "r"(b0_), "r"(b1_))

// cp.async (sm_80+, compute_100-safe)
#define CP_ASYNC16(dst, src) \
    asm volatile("cp.async.cg.shared.global [%0], [%1], 16;" \
                 :: "r"(dst), "l"(src) : "memory")
#define CP_COMMIT() asm volatile("cp.async.commit_group;" ::: "memory")
#define CP_WAIT0()  asm volatile("cp.async.wait_group 0;"  ::: "memory")

// ---------------------------------------------------------------------------
// Prepped W1 splits in device globals, ORIGINAL [K=256][N=256] layout
// (k-major is what the B-operand smem wants — no transpose). lo pre-scaled.
// ---------------------------------------------------------------------------
__device__ __align__(16) __half g_W1hi[256 * 256];
__device__ __align__(16) __half g_W1lo[256 * 256];

__global__ void prep_w1_kernel(const float* __restrict__ W1) {
    int idx = blockIdx.x * 256 + threadIdx.x;   // 0..65535
    float v  = W1[idx];
    __half hi = __float2half_rn(v);
    float  r  = (v - __half2float(hi)) * LO_SCALE;
    g_W1hi[idx] = hi;
    g_W1lo[idx] = __float2half_rn(r);
}

// ---------------------------------------------------------------------------
// SMEM layout (dynamic, ~197 KB)
// ---------------------------------------------------------------------------
#define OFF_B1P   0          // 128 float2 (b1 col-pairs)              1 KB
#define OFF_W2P   1024       // 128*5 float2 (W2 col-pairs x expert)   5 KB
#define OFF_B2    6144       // 5 floats
#define OFF_PART  6272       // [8 warpN][64 rows][5] floats          10 KB
#define OFF_AHI   16640      // 2 buf x [64 m][80B] (32 k fp16)       10 KB
#define OFF_ALO   26880      //                                       10 KB
#define OFF_BLO   37376      // 2 buf x [32 k][512B] (256 n fp16)     32 KB
#define OFF_W1HI  70144      // [256 k][512B] XOR-swizzled           128 KB
#define SMEM_BYTES 201216

#define NTHREADS 512

__global__ __launch_bounds__(NTHREADS, 1)
void gating_main(const float* __restrict__ x,
                 const float* __restrict__ b1,
                 const float* __restrict__ W2,
                 const float* __restrict__ b2,
                 float* __restrict__ gates_out,
                 float* __restrict__ idx_out,
                 int ntiles)
{
    extern __shared__ __align__(1024) char smem[];
    const uint32_t sb = smem_u32(smem);
    const int tid   = threadIdx.x;
    const int lane  = tid & 31;
    const int wid   = tid >> 5;
    const int warpM = wid >> 3;      // 0..1  (32 rows each)
    const int warpN = wid & 7;       // 0..7  (32 cols each)

    // ---- Stage small tensors ----
    if (tid < 128) {
        ((float2*)(smem + OFF_B1P))[tid] = make_float2(b1[2 * tid], b1[2 * tid + 1]);
    }
    for (int u = tid; u < 640; u += NTHREADS) {  // w2pair[p*5+e] = {W2[2p][e], W2[2p+1][e]}
        int p = u / 5, e = u - p * 5;
        ((float2*)(smem + OFF_W2P))[u] =
            make_float2(W2[2 * p * 5 + e], W2[(2 * p + 1) * 5 + e]);
    }
    if (tid < 5) ((float*)(smem + OFF_B2))[tid] = b2[tid];

    // ---- Stage resident W1hi: [k][n] fp16, 512B rows, 16B-chunk XOR swizzle ----
    #pragma unroll 4
    for (int i = 0; i < 16; i++) {
        int u = tid + NTHREADS * i;              // 8192 x 16B
        int k = u >> 5;
        int j = u & 31;                          // n-chunk (8 fp16)
        uint4 v = *((const uint4*)(g_W1hi) + (k * 32 + j));
        *(uint4*)(smem + OFF_W1HI + k * 512 + ((j ^ (k & 7)) << 4)) = v;
    }
    __syncthreads();

    // ---- Per-lane ldmatrix address components (mappings verified in v4) ----
    const int a_row  = lane & 15;                // row within m16
    const int a_col8 = (lane >> 4) << 4;         // 8-elem k group -> bytes
    const int b_krow = lane & 15;                // k row within k16
    const int b_n    = warpN * 32 + ((lane >> 4) << 3);  // +p*16 later

    // x load coords: thread -> (row 0..63, 4-float group 0..7)
    const int xrow = tid >> 3;
    const int xg   = tid & 7;

    // ------------------------------------------------------------------
    // Persistent tile loop: tiles of 64 rows.
    // ------------------------------------------------------------------
    for (int g = blockIdx.x; g < ntiles; g += gridDim.x) {
        const int m0 = g * 64;

        float acc_h[2][4][4];   // hi*hi
        float acc_x[2][4][4];   // hi*lo + lo*hi (scaled by 2^11)
        #pragma unroll
        for (int mi = 0; mi < 2; mi++)
            #pragma unroll
            for (int nf = 0; nf < 4; nf++)
                #pragma unroll
                for (int c = 0; c < 4; c++) { acc_h[mi][nf][c] = 0.f; acc_x[mi][nf][c] = 0.f; }

        float4 xr;              // 4 floats of x (prefetch regs)

        auto load_x = [&](int kc) {
            xr = *(const float4*)(x + (size_t)(m0 + xrow) * 256 + kc * 32 + xg * 4);
        };
        auto store_x = [&](int buf) {
            float vv[4] = {xr.x, xr.y, xr.z, xr.w};
            ushort hh[4], ll[4];
            #pragma unroll
            for (int p = 0; p < 4; p++) {
                __half h = __float2half_rn(vv[p]);
                __half l = __float2half_rn((vv[p] - __half2float(h)) * LO_SCALE);
                hh[p] = __half_as_ushort(h);
                ll[p] = __half_as_ushort(l);
            }
            uint2 hv = make_uint2((uint32_t)hh[0] | ((uint32_t)hh[1] << 16),
                                  (uint32_t)hh[2] | ((uint32_t)hh[3] << 16));
            uint2 lv = make_uint2((uint32_t)ll[0] | ((uint32_t)ll[1] << 16),
                                  (uint32_t)ll[2] | ((uint32_t)ll[3] << 16));
            *(uint2*)(smem + OFF_AHI + buf * 5120 + xrow * 80 + xg * 8) = hv;
            *(uint2*)(smem + OFF_ALO + buf * 5120 + xrow * 80 + xg * 8) = lv;
        };
        // W1lo chunk: 32k x 256n fp16 = 1024 x 16B, cp.async straight to SMEM.
        auto cp_blo = [&](int kc, int buf) {
            #pragma unroll
            for (int i = 0; i < 2; i++) {
                int u  = tid + NTHREADS * i;
                int kl = u >> 5;
                int j  = u & 31;
                uint32_t dst = sb + OFF_BLO + buf * 16384 + kl * 512 +
                               (uint32_t)((j ^ (kl & 7)) << 4);
                const uint4* src = (const uint4*)(g_W1lo) + ((kc * 32 + kl) * 32 + j);
                CP_ASYNC16(dst, src);
            }
            CP_COMMIT();
        };

        // Prologue: chunk 0 into buffer 0.
        load_x(0);
        cp_blo(0, 0);
        store_x(0);

        #pragma unroll 1
        for (int kc = 0; kc < 8; kc++) {
            const int buf = kc & 1;
            CP_WAIT0();                          // cp.async group for buf done
            __syncthreads();                     // cta-wide: STS + cp.async visible
            if (kc < 7) {
                load_x(kc + 1);                  // LDG first (earliest MLP)
                cp_blo(kc + 1, buf ^ 1);         // overlap with MMA block below
            }

            #pragma unroll
            for (int k16 = 0; k16 < 2; k16++) {
                uint32_t ah[2][4], al[2][4], bh[2][4], blr[2][4];
                #pragma unroll
                for (int mi = 0; mi < 2; mi++) {
                    uint32_t aoff = (uint32_t)((warpM * 32 + mi * 16 + a_row) * 80 +
                                               k16 * 32 + a_col8);
                    LDSM_X4(ah[mi], sb + OFF_AHI + buf * 5120 + aoff);
                    LDSM_X4(al[mi], sb + OFF_ALO + buf * 5120 + aoff);
                }
                #pragma unroll
                for (int p = 0; p < 2; p++) {
                    int n_col = b_n + p * 16;
                    int k_abs = kc * 32 + k16 * 16 + b_krow;
                    int k_loc = k16 * 16 + b_krow;
                    uint32_t hoff = (uint32_t)(k_abs * 512 +
                                               (((n_col >> 3) ^ (k_abs & 7)) << 4));
                    uint32_t loff = (uint32_t)(k_loc * 512 +
                                               (((n_col >> 3) ^ (k_loc & 7)) << 4));
                    LDSM_X4T(bh[p],  sb + OFF_W1HI + hoff);
                    LDSM_X4T(blr[p], sb + OFF_BLO + buf * 16384 + loff);
                }
                #pragma unroll
                for (int mi = 0; mi < 2; mi++) {
                    #pragma unroll
                    for (int p = 0; p < 2; p++) {
                        MMA(acc_h[mi][2 * p],     ah[mi], bh[p][0],  bh[p][1]);
                        MMA(acc_h[mi][2 * p + 1], ah[mi], bh[p][2],  bh[p][3]);
                        MMA(acc_x[mi][2 * p],     ah[mi], blr[p][0], blr[p][1]);
                        MMA(acc_x[mi][2 * p + 1], ah[mi], blr[p][2], blr[p][3]);
                        MMA(acc_x[mi][2 * p],     al[mi], bh[p][0],  bh[p][1]);
                        MMA(acc_x[mi][2 * p + 1], al[mi], bh[p][2],  bh[p][3]);
                    }
                }
            }
            if (kc < 7) store_x(buf ^ 1);        // other buffer; safe w/o extra sync
        }

        // -------------------- Epilogue --------------------
        const float2* b1pr = (const float2*)(smem + OFF_B1P);
        const float2* w2pr = (const float2*)(smem + OFF_W2P);

        float lg[4][5];
        #pragma unroll
        for (int r = 0; r < 4; r++)
            #pragma unroll
            for (int e = 0; e < 5; e++) lg[r][e] = 0.f;

        #pragma unroll
        for (int nf = 0; nf < 4; nf++) {
            const int pidx = warpN * 16 + nf * 4 + (lane & 3);   // col-pair 0..127
            const float2 b1p = b1pr[pidx];
            float2 w2v[5];
            #pragma unroll
            for (int e = 0; e < 5; e++) w2v[e] = w2pr[pidx * 5 + e];
            #pragma unroll
            for (int mi = 0; mi < 2; mi++) {
                #pragma unroll
                for (int ch = 0; ch < 2; ch++) {
                    float h0 = fmaxf(fmaf(acc_x[mi][nf][ch * 2 + 0], LO_INV,
                                          acc_h[mi][nf][ch * 2 + 0]) + b1p.x, 0.f);
                    float h1 = fmaxf(fmaf(acc_x[mi][nf][ch * 2 + 1], LO_INV,
                                          acc_h[mi][nf][ch * 2 + 1]) + b1p.y, 0.f);
                    const int r = mi * 2 + ch;
                    #pragma unroll
                    for (int e = 0; e < 5; e++)
                        lg[r][e] = fmaf(h1, w2v[e].y, fmaf(h0, w2v[e].x, lg[r][e]));
                }
            }
        }
        // quad reduce (4 col-pairs within warp share a row)
        #pragma unroll
        for (int r = 0; r < 4; r++)
            #pragma unroll
            for (int e = 0; e < 5; e++) {
                lg[r][e] += __shfl_xor_sync(0xFFFFFFFFu, lg[r][e], 1);
                lg[r][e] += __shfl_xor_sync(0xFFFFFFFFu, lg[r][e], 2);
            }
        float* part = (float*)(smem + OFF_PART);
        if ((lane & 3) == 0) {
            #pragma unroll
            for (int mi = 0; mi < 2; mi++)
                #pragma unroll
                for (int ch = 0; ch < 2; ch++) {
                    int row = warpM * 32 + mi * 16 + ch * 8 + (lane >> 2);
                    int r = mi * 2 + ch;
                    #pragma unroll
                    for (int e = 0; e < 5; e++)
                        part[(warpN * 64 + row) * 5 + e] = lg[r][e];
                }
        }
        __syncthreads();

        if (tid < 64) {
            const float* b2s = (const float*)(smem + OFF_B2);
            float l[5];
            #pragma unroll
            for (int e = 0; e < 5; e++) {
                float s0 = part[(0 * 64 + tid) * 5 + e] + part[(1 * 64 + tid) * 5 + e];
                float s1 = part[(2 * 64 + tid) * 5 + e] + part[(3 * 64 + tid) * 5 + e];
                float s2 = part[(4 * 64 + tid) * 5 + e] + part[(5 * 64 + tid) * 5 + e];
                float s3 = part[(6 * 64 + tid) * 5 + e] + part[(7 * 64 + tid) * 5 + e];
                l[e] = (s0 + s1) + (s2 + s3) + b2s[e];
            }

            // top-2, jax tie semantics (strict >, lowest index wins)
            float v1 = -3.4e38f, v2 = -3.4e38f;
            int i1 = -1, i2 = -1;
            #pragma unroll
            for (int e = 0; e < 5; e++) {
                if (l[e] > v1)      { v2 = v1; i2 = i1; v1 = l[e]; i1 = e; }
                else if (l[e] > v2) { v2 = l[e]; i2 = e; }
            }
            float e2v = expf(v2 - v1);
            float s   = 1.0f + e2v;
            float g1  = 1.0f / s;
            float g2  = e2v / s;

            size_t rg = (size_t)m0 + tid;
            if (gates_out) {
                #pragma unroll
                for (int e = 0; e < 5; e++) {
                    float gv = (e == i1) ? g1 : ((e == i2) ? g2 : 0.0f);
                    gates_out[rg * 5 + e] = gv;
                }
            }
            if (idx_out) {
                idx_out[rg * 2 + 0] = (float)i1;
                idx_out[rg * 2 + 1] = (float)i2;
            }
        }
        __syncthreads();   // protect 'part' and smem bufs before next tile
    }
}

// ---------------------------------------------------------------------------
// Launch. Inputs (metadata order): x, W1, b1, W2, b2.
// Output: gates [B*5] floats, then top_idx [B*2] as floats.
// ---------------------------------------------------------------------------
extern "C" void kernel_launch(void* const* d_in, const int* in_sizes, int n_in,
                              void* d_out, int out_size)
{
    const float* x  = (const float*)d_in[0];
    const float* W1 = (const float*)d_in[1];
    const float* b1 = (const float*)d_in[2];
    const float* W2 = (const float*)d_in[3];
    const float* b2 = (const float*)d_in[4];

    const int B = in_sizes[0] / 256;
    const int ntiles = B / 64;

    float* out       = (float*)d_out;
    float* gates_out = out;
    float* idx_out   = nullptr;
    if (out_size >= B * 7) {
        idx_out = out + (size_t)B * 5;          // gates then idx (concatenated)
    } else if (out_size == B * 2) {
        gates_out = nullptr;                    // idx only
        idx_out   = out;
    }                                           // else: gates only

    cudaFuncSetAttribute(gating_main,
                         cudaFuncAttributeMaxDynamicSharedMemorySize, SMEM_BYTES);

    prep_w1_kernel<<<256, 256>>>(W1);

    int grid = 148;
    if (grid > ntiles) grid = ntiles;
    gating_main<<<grid, NTHREADS, SMEM_BYTES>>>(x, b1, W2, b2, gates_out, idx_out, ntiles);
}